// round 6
// baseline (speedup 1.0000x reference)
#include <cuda_runtime.h>
#include <cstdint>

// ---------------------------------------------------------------------------
// FloodGNN: 2-layer GraphSAGE + linear head, transform-then-aggregate.
// R6: stream-fork overlaps CSR build with layer-1 GEMM; gather<0> fuses the
// layer-2 activation (h = relu(mean*inv + z)), making both GEMMs identical;
// vectorized build; gather unrolled x8.
// ---------------------------------------------------------------------------

constexpr int N_NODES = 100000;
constexpr int E_EDGES = 1600000;
constexpr int IN_DIM  = 128;
constexpr int HID     = 64;
constexpr int STRIDE  = 96;   // neighbor bucket capacity (deg ~ Binomial, mean 16)

__device__ int   g_cnt[N_NODES];                    // per-dst degree / cursor
__device__ int   g_csr[(size_t)N_NODES * STRIDE];   // neighbor src ids
__device__ float g_y  [(size_t)N_NODES * HID];      // feat @ W_l
__device__ float g_z  [(size_t)N_NODES * HID];      // feat @ W_r + b
__device__ float g_h  [(size_t)N_NODES * HID];      // layer-2 input features

// ---------------------------------------------------------------------------
__global__ void k_zero_cnt() {
    int i = blockIdx.x * blockDim.x + threadIdx.x;
    if (i < N_NODES / 4)
        reinterpret_cast<int4*>(g_cnt)[i] = make_int4(0, 0, 0, 0);
}

// CSR bucket build, 4 edges per thread; also produces degrees in g_cnt.
__global__ void k_build(const int* __restrict__ ei) {
    int i = blockIdx.x * blockDim.x + threadIdx.x;
    if (i >= E_EDGES / 4) return;
    int4 s = __ldg(reinterpret_cast<const int4*>(ei) + i);
    int4 d = __ldg(reinterpret_cast<const int4*>(ei + E_EDGES) + i);
    int slot;
    slot = atomicAdd(&g_cnt[d.x], 1); if (slot < STRIDE) g_csr[(size_t)d.x * STRIDE + slot] = s.x;
    slot = atomicAdd(&g_cnt[d.y], 1); if (slot < STRIDE) g_csr[(size_t)d.y * STRIDE + slot] = s.y;
    slot = atomicAdd(&g_cnt[d.z], 1); if (slot < STRIDE) g_csr[(size_t)d.z * STRIDE + slot] = s.z;
    slot = atomicAdd(&g_cnt[d.w], 1); if (slot < STRIDE) g_csr[(size_t)d.w * STRIDE + slot] = s.w;
}

// ---------------------------------------------------------------------------
// Packed f32x2 FMA (Blackwell FFMA2): d = a*b + c on (lo,hi) float pairs.
// ---------------------------------------------------------------------------
__device__ __forceinline__ unsigned long long ffma2(
    unsigned long long a, unsigned long long b, unsigned long long c)
{
    unsigned long long d;
    asm("fma.rn.f32x2 %0, %1, %2, %3;" : "=l"(d) : "l"(a), "l"(b), "l"(c));
    return d;
}

// ---------------------------------------------------------------------------
// GEMM transform: per 128-row block,
//   g_y[row] = xin[row] @ Wl ;  g_z[row] = xin[row] @ Wr + bias
// 256 threads; thread (tx,ty) computes an 8x8 micro-tile as 32 f32x2 pairs.
// xin staged in smem pre-duplicated as (v,v) pairs; W pairs = adjacent cols.
// ---------------------------------------------------------------------------
template <int K>
__global__ void __launch_bounds__(256, 2) k_gemm(
    const float* __restrict__ xin,
    const float* __restrict__ Wl,
    const float* __restrict__ Wr,
    const float* __restrict__ bias)
{
    constexpr int KB = 16;
    constexpr int NSLAB = K / KB;
    __shared__ float2 xs[128][KB + 2];
    __shared__ float  ws[KB][128];

    const int tid = threadIdx.x;
    const int tx = tid & 15;
    const int ty = tid >> 4;
    const int row0 = blockIdx.x * 128;

    unsigned long long acc[8][4];
    #pragma unroll
    for (int r = 0; r < 8; r++)
        #pragma unroll
        for (int c = 0; c < 4; c++) acc[r][c] = 0ULL;

    for (int slab = 0; slab < NSLAB; slab++) {
        const int k0 = slab * KB;
        __syncthreads();

        #pragma unroll
        for (int i = 0; i < 2; i++) {
            int v  = tid + i * 256;
            int kk = v >> 5;
            int cs = v & 31;
            int gk = k0 + kk;
            float4 w;
            if (cs < 16) w = *reinterpret_cast<const float4*>(&Wl[gk * HID + cs * 4]);
            else         w = *reinterpret_cast<const float4*>(&Wr[gk * HID + (cs - 16) * 4]);
            *reinterpret_cast<float4*>(&ws[kk][cs * 4]) = w;
        }

        #pragma unroll
        for (int i = 0; i < 2; i++) {
            int v   = tid + i * 256;
            int row = v >> 2;
            int kq  = v & 3;
            int grow = row0 + row;
            float4 xv = make_float4(0.f, 0.f, 0.f, 0.f);
            if (grow < N_NODES)
                xv = *reinterpret_cast<const float4*>(&xin[(size_t)grow * K + k0 + kq * 4]);
            xs[row][kq * 4 + 0] = make_float2(xv.x, xv.x);
            xs[row][kq * 4 + 1] = make_float2(xv.y, xv.y);
            xs[row][kq * 4 + 2] = make_float2(xv.z, xv.z);
            xs[row][kq * 4 + 3] = make_float2(xv.w, xv.w);
        }
        __syncthreads();

        #pragma unroll
        for (int kk = 0; kk < KB; kk += 2) {
            ulonglong2 w0a = *reinterpret_cast<const ulonglong2*>(&ws[kk][tx * 8]);
            ulonglong2 w0b = *reinterpret_cast<const ulonglong2*>(&ws[kk][tx * 8 + 4]);
            ulonglong2 w1a = *reinterpret_cast<const ulonglong2*>(&ws[kk + 1][tx * 8]);
            ulonglong2 w1b = *reinterpret_cast<const ulonglong2*>(&ws[kk + 1][tx * 8 + 4]);
            #pragma unroll
            for (int r = 0; r < 8; r++) {
                ulonglong2 a = *reinterpret_cast<const ulonglong2*>(&xs[ty * 8 + r][kk]);
                acc[r][0] = ffma2(a.x, w0a.x, acc[r][0]);
                acc[r][1] = ffma2(a.x, w0a.y, acc[r][1]);
                acc[r][2] = ffma2(a.x, w0b.x, acc[r][2]);
                acc[r][3] = ffma2(a.x, w0b.y, acc[r][3]);
                acc[r][0] = ffma2(a.y, w1a.x, acc[r][0]);
                acc[r][1] = ffma2(a.y, w1a.y, acc[r][1]);
                acc[r][2] = ffma2(a.y, w1b.x, acc[r][2]);
                acc[r][3] = ffma2(a.y, w1b.y, acc[r][3]);
            }
        }
    }

    float b0 = 0.f, b1 = 0.f, b2 = 0.f, b3 = 0.f, b4 = 0.f, b5 = 0.f, b6 = 0.f, b7 = 0.f;
    if (tx >= 8) {
        int cb = tx * 8 - 64;
        float4 bb0 = *reinterpret_cast<const float4*>(&bias[cb]);
        float4 bb1 = *reinterpret_cast<const float4*>(&bias[cb + 4]);
        b0 = bb0.x; b1 = bb0.y; b2 = bb0.z; b3 = bb0.w;
        b4 = bb1.x; b5 = bb1.y; b6 = bb1.z; b7 = bb1.w;
    }
    #pragma unroll
    for (int r = 0; r < 8; r++) {
        int grow = row0 + ty * 8 + r;
        if (grow >= N_NODES) break;
        float2 c0 = *reinterpret_cast<float2*>(&acc[r][0]);
        float2 c1 = *reinterpret_cast<float2*>(&acc[r][1]);
        float2 c2 = *reinterpret_cast<float2*>(&acc[r][2]);
        float2 c3 = *reinterpret_cast<float2*>(&acc[r][3]);
        if (tx < 8) {
            float4 v0 = make_float4(c0.x, c0.y, c1.x, c1.y);
            float4 v1 = make_float4(c2.x, c2.y, c3.x, c3.y);
            size_t base = (size_t)grow * HID + tx * 8;
            *reinterpret_cast<float4*>(&g_y[base])     = v0;
            *reinterpret_cast<float4*>(&g_y[base + 4]) = v1;
        } else {
            float4 v0 = make_float4(c0.x + b0, c0.y + b1, c1.x + b2, c1.y + b3);
            float4 v1 = make_float4(c2.x + b4, c2.y + b5, c3.x + b6, c3.y + b7);
            size_t base = (size_t)grow * HID + (tx * 8 - 64);
            *reinterpret_cast<float4*>(&g_z[base])     = v0;
            *reinterpret_cast<float4*>(&g_z[base + 4]) = v1;
        }
    }
}

// ---------------------------------------------------------------------------
// CSR gather: 16 threads per dst row; thread owns one float4 slice.
// acc = sum over neighbors of g_y[src]; then:
//   FINAL=false: g_h[dst] = relu(acc*inv + g_z[dst])      (layer-2 input)
//   FINAL=true : h = relu(acc*inv + z); out = h @ Wc + bc (fused head)
// Neighbor loop unrolled x8 (int4 index preloads) for load-level parallelism.
// ---------------------------------------------------------------------------
template <bool FINAL>
__global__ void __launch_bounds__(256) k_gather(const float* __restrict__ Wc,
                                                const float* __restrict__ bc,
                                                float* __restrict__ out)
{
    int t = blockIdx.x * blockDim.x + threadIdx.x;
    int dst = t >> 4;
    int part = t & 15;
    if (dst >= N_NODES) return;

    int deg = g_cnt[dst];
    int n = deg < STRIDE ? deg : STRIDE;
    const int* lst = &g_csr[(size_t)dst * STRIDE];

    float4 acc = make_float4(0.f, 0.f, 0.f, 0.f);
    int j = 0;
    for (; j + 8 <= n; j += 8) {
        int4 i0 = __ldg(reinterpret_cast<const int4*>(lst + j));
        int4 i1 = __ldg(reinterpret_cast<const int4*>(lst + j + 4));
        float4 v0 = *reinterpret_cast<const float4*>(&g_y[(size_t)i0.x * HID + part * 4]);
        float4 v1 = *reinterpret_cast<const float4*>(&g_y[(size_t)i0.y * HID + part * 4]);
        float4 v2 = *reinterpret_cast<const float4*>(&g_y[(size_t)i0.z * HID + part * 4]);
        float4 v3 = *reinterpret_cast<const float4*>(&g_y[(size_t)i0.w * HID + part * 4]);
        float4 v4 = *reinterpret_cast<const float4*>(&g_y[(size_t)i1.x * HID + part * 4]);
        float4 v5 = *reinterpret_cast<const float4*>(&g_y[(size_t)i1.y * HID + part * 4]);
        float4 v6 = *reinterpret_cast<const float4*>(&g_y[(size_t)i1.z * HID + part * 4]);
        float4 v7 = *reinterpret_cast<const float4*>(&g_y[(size_t)i1.w * HID + part * 4]);
        acc.x += (v0.x + v1.x) + (v2.x + v3.x) + (v4.x + v5.x) + (v6.x + v7.x);
        acc.y += (v0.y + v1.y) + (v2.y + v3.y) + (v4.y + v5.y) + (v6.y + v7.y);
        acc.z += (v0.z + v1.z) + (v2.z + v3.z) + (v4.z + v5.z) + (v6.z + v7.z);
        acc.w += (v0.w + v1.w) + (v2.w + v3.w) + (v4.w + v5.w) + (v6.w + v7.w);
    }
    for (; j + 4 <= n; j += 4) {
        int4 i0 = __ldg(reinterpret_cast<const int4*>(lst + j));
        float4 v0 = *reinterpret_cast<const float4*>(&g_y[(size_t)i0.x * HID + part * 4]);
        float4 v1 = *reinterpret_cast<const float4*>(&g_y[(size_t)i0.y * HID + part * 4]);
        float4 v2 = *reinterpret_cast<const float4*>(&g_y[(size_t)i0.z * HID + part * 4]);
        float4 v3 = *reinterpret_cast<const float4*>(&g_y[(size_t)i0.w * HID + part * 4]);
        acc.x += (v0.x + v1.x) + (v2.x + v3.x);
        acc.y += (v0.y + v1.y) + (v2.y + v3.y);
        acc.z += (v0.z + v1.z) + (v2.z + v3.z);
        acc.w += (v0.w + v1.w) + (v2.w + v3.w);
    }
    for (; j < n; j++) {
        int s = __ldg(&lst[j]);
        float4 v = *reinterpret_cast<const float4*>(&g_y[(size_t)s * HID + part * 4]);
        acc.x += v.x; acc.y += v.y; acc.z += v.z; acc.w += v.w;
    }

    float inv = 1.0f / fmaxf((float)deg, 1.0f);
    float4 zv = *reinterpret_cast<const float4*>(&g_z[(size_t)dst * HID + part * 4]);
    float h0 = fmaxf(fmaf(acc.x, inv, zv.x), 0.f);
    float h1 = fmaxf(fmaf(acc.y, inv, zv.y), 0.f);
    float h2 = fmaxf(fmaf(acc.z, inv, zv.z), 0.f);
    float h3 = fmaxf(fmaf(acc.w, inv, zv.w), 0.f);

    if (!FINAL) {
        *reinterpret_cast<float4*>(&g_h[(size_t)dst * HID + part * 4]) =
            make_float4(h0, h1, h2, h3);
    } else {
        float4 wc = *reinterpret_cast<const float4*>(&Wc[part * 4]);
        float s = h0 * wc.x + h1 * wc.y + h2 * wc.z + h3 * wc.w;
        #pragma unroll
        for (int o = 8; o > 0; o >>= 1)
            s += __shfl_down_sync(0xffffffffu, s, o, 16);
        if (part == 0) out[dst] = s + __ldg(&bc[0]);
    }
}

// ---------------------------------------------------------------------------
extern "C" void kernel_launch(void* const* d_in, const int* in_sizes, int n_in,
                              void* d_out, int out_size)
{
    const float* x   = (const float*)d_in[0];
    const int*   ei  = (const int*)  d_in[1];
    const float* W1l = (const float*)d_in[2];
    const float* W1r = (const float*)d_in[3];
    const float* b1  = (const float*)d_in[4];
    const float* W2l = (const float*)d_in[5];
    const float* W2r = (const float*)d_in[6];
    const float* b2  = (const float*)d_in[7];
    const float* Wc  = (const float*)d_in[8];
    const float* bc  = (const float*)d_in[9];
    float* out = (float*)d_out;

    void* h_ptr = nullptr;
    cudaGetSymbolAddress(&h_ptr, g_h);          // host-side query, no alloc

    constexpr int ZC_BLKS    = (N_NODES / 4 + 255) / 256;                  // 98
    constexpr int BUILD_BLKS = (E_EDGES / 4 + 255) / 256;                  // 1563
    constexpr int GEMM_BLKS  = (N_NODES + 127) / 128;                      // 782
    constexpr int GATH_BLKS  = (int)(((size_t)N_NODES * 16 + 255) / 256);  // 6250

    // Fork a side stream so [zero_cnt -> build] overlaps gemm1 (independent).
    cudaStream_t s2;
    cudaEvent_t evFork, evJoin;
    cudaStreamCreateWithFlags(&s2, cudaStreamNonBlocking);
    cudaEventCreateWithFlags(&evFork, cudaEventDisableTiming);
    cudaEventCreateWithFlags(&evJoin, cudaEventDisableTiming);

    cudaEventRecord(evFork, 0);
    cudaStreamWaitEvent(s2, evFork, 0);
    k_zero_cnt<<<ZC_BLKS, 256, 0, s2>>>();
    k_build<<<BUILD_BLKS, 256, 0, s2>>>(ei);
    cudaEventRecord(evJoin, s2);

    k_gemm<IN_DIM><<<GEMM_BLKS, 256>>>(x, W1l, W1r, b1);      // main stream

    cudaStreamWaitEvent(0, evJoin, 0);                        // join before gather
    k_gather<false><<<GATH_BLKS, 256>>>(nullptr, nullptr, nullptr);
    k_gemm<HID><<<GEMM_BLKS, 256>>>((const float*)h_ptr, W2l, W2r, b2);
    k_gather<true><<<GATH_BLKS, 256>>>(Wc, bc, out);

    cudaEventDestroy(evFork);
    cudaEventDestroy(evJoin);
    cudaStreamDestroy(s2);
}